// round 7
// baseline (speedup 1.0000x reference)
#include <cuda_runtime.h>
#include <cuda_bf16.h>
#include <cstdint>

// ---------------------------------------------------------------------------
// Problem constants
// ---------------------------------------------------------------------------
#define B_DIM 4096
#define H_DIM 1024
#define N_GATES 4096       // 4*H
#define K_DIM  2048        // D + H

// GEMM tiling
#define BM 128
#define BN 64
#define BK 32
#define STAGES 4
#define NT (K_DIM / BK)    // 64 k-tiles
#define NTHREADS 256

// smem per stage: Ahi/Alo 128x64B + Bhi/Blo 64x64B = 24576 B
#define A_TILE_BYTES 8192
#define B_TILE_BYTES 4096
#define STAGE_BYTES (2 * A_TILE_BYTES + 2 * B_TILE_BYTES)   // 24576
#define OFF_ALO A_TILE_BYTES
#define OFF_BHI (2 * A_TILE_BYTES)
#define OFF_BLO (2 * A_TILE_BYTES + B_TILE_BYTES)
#define SMEM_TOTAL (STAGES * STAGE_BYTES)                   // 98304 -> 2 CTAs/SM

// ---------------------------------------------------------------------------
// Scratch (device globals; no runtime allocation)
// gB* hold the GATE-INTERLEAVED weight layout: row n' = j*4 + g  (orig g*H + j)
// ---------------------------------------------------------------------------
__device__ __nv_bfloat16 gAhi[(size_t)B_DIM * K_DIM];
__device__ __nv_bfloat16 gAlo[(size_t)B_DIM * K_DIM];
__device__ __nv_bfloat16 gBhi[(size_t)N_GATES * K_DIM];
__device__ __nv_bfloat16 gBlo[(size_t)N_GATES * K_DIM];
__device__ float gBias[N_GATES];   // permuted b_ih + b_hh

// ---------------------------------------------------------------------------
// PTX helpers (sm_80+ portable)
// ---------------------------------------------------------------------------
__device__ __forceinline__ uint32_t smem_u32(const void* p) {
    uint32_t a;
    asm("{ .reg .u64 t; cvta.to.shared.u64 t, %1; cvt.u32.u64 %0, t; }" : "=r"(a) : "l"(p));
    return a;
}

#define CP_ASYNC16(dst, src) \
    asm volatile("cp.async.cg.shared.global [%0], [%1], 16;" \
                 :: "r"(dst), "l"(src) : "memory")
#define CP_COMMIT() asm volatile("cp.async.commit_group;" ::: "memory")
#define CP_WAIT(n)  asm volatile("cp.async.wait_group %0;" :: "n"(n) : "memory")

#define LDSM_X4(r, addr) \
    asm volatile("ldmatrix.sync.aligned.m8n8.x4.shared.b16 {%0,%1,%2,%3}, [%4];" \
                 : "=r"((r)[0]), "=r"((r)[1]), "=r"((r)[2]), "=r"((r)[3]) : "r"(addr))

__device__ __forceinline__ void mma_bf16(float* d, const uint32_t* a, const uint32_t* b) {
    asm volatile(
        "mma.sync.aligned.m16n8k16.row.col.f32.bf16.bf16.f32 "
        "{%0,%1,%2,%3}, {%4,%5,%6,%7}, {%8,%9}, {%0,%1,%2,%3};"
        : "+f"(d[0]), "+f"(d[1]), "+f"(d[2]), "+f"(d[3])
        : "r"(a[0]), "r"(a[1]), "r"(a[2]), "r"(a[3]), "r"(b[0]), "r"(b[1]));
}

__device__ __forceinline__ float sigmoidf_(float v) {
    return 1.0f / (1.0f + __expf(-v));
}

// ---------------------------------------------------------------------------
// Combined conversion kernel:
//   blocks [0, 8192):      A = [x | h0]  -> gAhi/gAlo   (row-identity)
//   blocks [8192, 16384):  B = [wih|whh] -> gBhi/gBlo   (rows permuted j*4+g)
//   blocks [16384, 16400): permuted bias sum
// ---------------------------------------------------------------------------
__global__ __launch_bounds__(256)
void convert_all(const float* __restrict__ x,   const float* __restrict__ h0,
                 const float* __restrict__ wih, const float* __restrict__ whh,
                 const float* __restrict__ b_ih, const float* __restrict__ b_hh)
{
    const int bid = blockIdx.x;
    const int tid = threadIdx.x;

    if (bid >= 16384) {                       // bias
        const int np = (bid - 16384) * 256 + tid;        // 0..4095
        const int r = ((np & 3) << 10) | (np >> 2);      // orig row g*1024+j
        gBias[np] = b_ih[r] + b_hh[r];
        return;
    }

    const bool isA = (bid < 8192);
    const int idx = (isA ? bid : bid - 8192) * 256 + tid;  // 4-elem group id
    const int row = idx >> 9;                              // output row
    const int col = (idx & 511) << 2;                      // K column

    int srow = row;
    const float *s0, *s1;
    if (isA) { s0 = x; s1 = h0; }
    else     { s0 = wih; s1 = whh; srow = ((row & 3) << 10) | (row >> 2); }

    const float* src = (col < 1024) ? (s0 + (size_t)srow * 1024 + col)
                                    : (s1 + (size_t)srow * 1024 + (col - 1024));
    float4 v = *reinterpret_cast<const float4*>(src);
    float f[4] = {v.x, v.y, v.z, v.w};
    __nv_bfloat16 hb[4], lb[4];
    #pragma unroll
    for (int j = 0; j < 4; j++) {
        hb[j] = __float2bfloat16(f[j]);
        lb[j] = __float2bfloat16(f[j] - __bfloat162float(hb[j]));
    }
    __nv_bfloat16* hi = isA ? gAhi : gBhi;
    __nv_bfloat16* lo = isA ? gAlo : gBlo;
    const size_t o = (size_t)row * K_DIM + col;
    *reinterpret_cast<__nv_bfloat162*>(hi + o)     = __nv_bfloat162(hb[0], hb[1]);
    *reinterpret_cast<__nv_bfloat162*>(hi + o + 2) = __nv_bfloat162(hb[2], hb[3]);
    *reinterpret_cast<__nv_bfloat162*>(lo + o)     = __nv_bfloat162(lb[0], lb[1]);
    *reinterpret_cast<__nv_bfloat162*>(lo + o + 2) = __nv_bfloat162(lb[2], lb[3]);
}

// ---------------------------------------------------------------------------
// Fused GEMM + LSTM epilogue.
//   gates = Ahi*Bhi^T + Ahi*Blo^T + Alo*Bhi^T  (gate-interleaved columns)
//   then per (b, j): c = sig(f)*c0 + sig(i)*tanh(g); h = sig(o)*tanh(c)
//
// SMEM tile layout: rows x 4 16B-chunks, chunk' = chunk ^ ((row>>1)&3).
// Conflict-free for both cp.async 16B stores and ldmatrix reads.
// 2048 CTAs (vs 1024) -> tail-drain loss ~7% instead of ~14%.
// ---------------------------------------------------------------------------
__global__ __launch_bounds__(NTHREADS, 2)
void lstm_gemm_fused(const float* __restrict__ c0, float* __restrict__ out)
{
    extern __shared__ char smem[];
    const uint32_t sb = smem_u32(smem);
    const int tid  = threadIdx.x;
    const int wid  = tid >> 5;
    const int lane = tid & 31;
    const int warp_m = wid >> 1;    // 0..3
    const int warp_n = wid & 1;     // 0..1

    const int bm = blockIdx.y * BM;
    const int bn = blockIdx.x * BN;

    float acc[2][4][4];
    #pragma unroll
    for (int mt = 0; mt < 2; mt++)
        #pragma unroll
        for (int nt = 0; nt < 4; nt++)
            #pragma unroll
            for (int j = 0; j < 4; j++)
                acc[mt][nt][j] = 0.0f;

    // ---- ldmatrix addressing ----
    const int a_row = warp_m * 32 + (lane & 15);
    const int s_a   = (a_row >> 1) & 3;
    const int a_c0  = lane >> 4;                              // 0/1
    const int b_row = warp_n * 32 + ((lane >> 4) << 3) + (lane & 7);
    const int s_b   = (b_row >> 1) & 3;
    const int b_c0  = (lane >> 3) & 1;

    // ---- cp.async addressing ----
    const int r0 = tid >> 2;                 // 0..63
    const int cc = tid & 3;                  // 16B chunk
    const uint32_t dstoff = (uint32_t)(r0 * 64 + ((cc ^ ((r0 >> 1) & 3)) << 4));
    const __nv_bfloat16* pAhi = gAhi + (size_t)(bm + r0) * K_DIM + cc * 8;
    const __nv_bfloat16* pAlo = gAlo + (size_t)(bm + r0) * K_DIM + cc * 8;
    const __nv_bfloat16* pBhi = gBhi + (size_t)(bn + r0) * K_DIM + cc * 8;
    const __nv_bfloat16* pBlo = gBlo + (size_t)(bn + r0) * K_DIM + cc * 8;
    const size_t HSTEP = (size_t)64 * K_DIM;   // +64 rows (A tile second half)

    #define LOAD_STAGE(bufidx, k0) do {                                         \
        const uint32_t s_ = sb + (bufidx) * STAGE_BYTES + dstoff;               \
        CP_ASYNC16(s_,                      pAhi + (k0));                       \
        CP_ASYNC16(s_ + 4096,               pAhi + (k0) + HSTEP);               \
        CP_ASYNC16(s_ + OFF_ALO,            pAlo + (k0));                       \
        CP_ASYNC16(s_ + OFF_ALO + 4096,     pAlo + (k0) + HSTEP);               \
        CP_ASYNC16(s_ + OFF_BHI,            pBhi + (k0));                       \
        CP_ASYNC16(s_ + OFF_BLO,            pBlo + (k0));                       \
    } while (0)

    // prologue: stages 0,1,2
    LOAD_STAGE(0, 0);
    CP_COMMIT();
    LOAD_STAGE(1, BK);
    CP_COMMIT();
    LOAD_STAGE(2, 2 * BK);
    CP_COMMIT();

    for (int t = 0; t < NT; t++) {
        CP_WAIT(2);
        __syncthreads();
        if (t + 3 < NT)
            LOAD_STAGE((t + 3) & 3, (t + 3) * BK);
        CP_COMMIT();

        const uint32_t stage = sb + (t & 3) * STAGE_BYTES;
        #pragma unroll
        for (int ks = 0; ks < 2; ks++) {
            uint32_t a_hi[2][4], a_lo[2][4];
            const int ca = ((ks * 2 + a_c0) ^ s_a) << 4;
            #pragma unroll
            for (int mt = 0; mt < 2; mt++) {
                const uint32_t aa = stage + (a_row + mt * 16) * 64 + ca;
                LDSM_X4(a_hi[mt], aa);
                LDSM_X4(a_lo[mt], aa + OFF_ALO);
            }
            const int cb = ((ks * 2 + b_c0) ^ s_b) << 4;
            #pragma unroll
            for (int g = 0; g < 2; g++) {
                uint32_t b_hi[4], b_lo[4];
                const uint32_t ba = stage + OFF_BHI + (b_row + g * 16) * 64 + cb;
                LDSM_X4(b_hi, ba);
                LDSM_X4(b_lo, ba + B_TILE_BYTES);
                // Pass-major: accumulator reuse distance = 4 MMAs
                #pragma unroll
                for (int mt = 0; mt < 2; mt++)
                    #pragma unroll
                    for (int h = 0; h < 2; h++)
                        mma_bf16(acc[mt][g * 2 + h], a_hi[mt], &b_hi[h * 2]);
                #pragma unroll
                for (int mt = 0; mt < 2; mt++)
                    #pragma unroll
                    for (int h = 0; h < 2; h++)
                        mma_bf16(acc[mt][g * 2 + h], a_hi[mt], &b_lo[h * 2]);
                #pragma unroll
                for (int mt = 0; mt < 2; mt++)
                    #pragma unroll
                    for (int h = 0; h < 2; h++)
                        mma_bf16(acc[mt][g * 2 + h], a_lo[mt], &b_hi[h * 2]);
            }
        }
    }

    // ---- fused LSTM epilogue ----
    const int q = lane & 3;
    const bool is_if = ((q & 1) == 0);

    float bsum[4][2];
    #pragma unroll
    for (int nt = 0; nt < 4; nt++) {
        const int c = bn + warp_n * 32 + nt * 8 + q * 2;
        bsum[nt][0] = gBias[c];
        bsum[nt][1] = gBias[c + 1];
    }

    #pragma unroll
    for (int mt = 0; mt < 2; mt++) {
        const int r = bm + warp_m * 32 + mt * 16 + (lane >> 2);
        #pragma unroll
        for (int nt = 0; nt < 4; nt++) {
            float v0 = acc[mt][nt][0] + bsum[nt][0];
            float v1 = acc[mt][nt][1] + bsum[nt][1];
            float v2 = acc[mt][nt][2] + bsum[nt][0];
            float v3 = acc[mt][nt][3] + bsum[nt][1];
            const float o0 = __shfl_xor_sync(0xffffffffu, v0, 1);
            const float o1 = __shfl_xor_sync(0xffffffffu, v1, 1);
            const float o2 = __shfl_xor_sync(0xffffffffu, v2, 1);
            const float o3 = __shfl_xor_sync(0xffffffffu, v3, 1);

            const float gi0 = is_if ? v0 : o0;
            const float gf0 = is_if ? v1 : o1;
            const float gg0 = is_if ? o0 : v0;
            const float go0 = is_if ? o1 : v1;
            const float gi1 = is_if ? v2 : o2;
            const float gf1 = is_if ? v3 : o3;
            const float gg1 = is_if ? o2 : v2;
            const float go1 = is_if ? o3 : v3;

            const int j = (bn >> 2) + warp_n * 8 + nt * 2 + (q >> 1);
            const float c0v0 = c0[(size_t)r * H_DIM + j];
            const float c0v1 = c0[(size_t)(r + 8) * H_DIM + j];

            const float cn0 = sigmoidf_(gf0) * c0v0 + sigmoidf_(gi0) * tanhf(gg0);
            const float cn1 = sigmoidf_(gf1) * c0v1 + sigmoidf_(gi1) * tanhf(gg1);
            const float hn0 = sigmoidf_(go0) * tanhf(cn0);
            const float hn1 = sigmoidf_(go1) * tanhf(cn1);

            if (is_if) {
                out[(size_t)r * H_DIM + j]       = hn0;
                out[(size_t)(r + 8) * H_DIM + j] = hn1;
            } else {
                out[(size_t)B_DIM * H_DIM + (size_t)r * H_DIM + j]       = cn0;
                out[(size_t)B_DIM * H_DIM + (size_t)(r + 8) * H_DIM + j] = cn1;
            }
        }
    }
    #undef LOAD_STAGE
}

// ---------------------------------------------------------------------------
// Launch
// ---------------------------------------------------------------------------
extern "C" void kernel_launch(void* const* d_in, const int* in_sizes, int n_in,
                              void* d_out, int out_size)
{
    const float* x    = (const float*)d_in[0];
    const float* h0   = (const float*)d_in[1];
    const float* c0   = (const float*)d_in[2];
    const float* wih  = (const float*)d_in[3];
    const float* whh  = (const float*)d_in[4];
    const float* b_ih = (const float*)d_in[5];
    const float* b_hh = (const float*)d_in[6];
    float* out = (float*)d_out;

    cudaFuncSetAttribute(lstm_gemm_fused,
                         cudaFuncAttributeMaxDynamicSharedMemorySize, SMEM_TOTAL);

    convert_all<<<16400, 256>>>(x, h0, wih, whh, b_ih, b_hh);

    dim3 grid(N_GATES / BN, B_DIM / BM);                 // (64, 32) = 2048 CTAs
    lstm_gemm_fused<<<grid, NTHREADS, SMEM_TOTAL>>>(c0, out);
}

// round 8
// speedup vs baseline: 1.0683x; 1.0683x over previous
#include <cuda_runtime.h>
#include <cuda_bf16.h>
#include <cstdint>

// ---------------------------------------------------------------------------
// Problem constants
// ---------------------------------------------------------------------------
#define B_DIM 4096
#define H_DIM 1024
#define N_GATES 4096       // 4*H
#define K_DIM  2048        // D + H

// GEMM tiling: BN=64 small-footprint tile, 3 CTAs/SM
#define BM 128
#define BN 64
#define BK 32
#define STAGES 3
#define NT (K_DIM / BK)    // 64 k-tiles
#define NTHREADS 256

// smem per stage: Ahi/Alo 128x64B + Bhi/Blo 64x64B = 24576 B
#define A_TILE_BYTES 8192
#define B_TILE_BYTES 4096
#define STAGE_BYTES (2 * A_TILE_BYTES + 2 * B_TILE_BYTES)   // 24576
#define OFF_ALO A_TILE_BYTES
#define OFF_BHI (2 * A_TILE_BYTES)
#define OFF_BLO (2 * A_TILE_BYTES + B_TILE_BYTES)
#define SMEM_TOTAL (STAGES * STAGE_BYTES)                   // 73728 -> 3 CTAs/SM

// ---------------------------------------------------------------------------
// Scratch (device globals; no runtime allocation)
// gB* hold the GATE-INTERLEAVED weight layout: row n' = j*4 + g  (orig g*H + j)
// ---------------------------------------------------------------------------
__device__ __nv_bfloat16 gAhi[(size_t)B_DIM * K_DIM];
__device__ __nv_bfloat16 gAlo[(size_t)B_DIM * K_DIM];
__device__ __nv_bfloat16 gBhi[(size_t)N_GATES * K_DIM];
__device__ __nv_bfloat16 gBlo[(size_t)N_GATES * K_DIM];
__device__ float gBias[N_GATES];   // permuted b_ih + b_hh

// ---------------------------------------------------------------------------
// PTX helpers (sm_80+ portable)
// ---------------------------------------------------------------------------
__device__ __forceinline__ uint32_t smem_u32(const void* p) {
    uint32_t a;
    asm("{ .reg .u64 t; cvta.to.shared.u64 t, %1; cvt.u32.u64 %0, t; }" : "=r"(a) : "l"(p));
    return a;
}

#define CP_ASYNC16(dst, src) \
    asm volatile("cp.async.cg.shared.global [%0], [%1], 16;" \
                 :: "r"(dst), "l"(src) : "memory")
#define CP_COMMIT() asm volatile("cp.async.commit_group;" ::: "memory")
#define CP_WAIT(n)  asm volatile("cp.async.wait_group %0;" :: "n"(n) : "memory")

#define LDSM_X4(r, addr) \
    asm volatile("ldmatrix.sync.aligned.m8n8.x4.shared.b16 {%0,%1,%2,%3}, [%4];" \
                 : "=r"((r)[0]), "=r"((r)[1]), "=r"((r)[2]), "=r"((r)[3]) : "r"(addr))

__device__ __forceinline__ void mma_bf16(float* d, const uint32_t* a, const uint32_t* b) {
    asm volatile(
        "mma.sync.aligned.m16n8k16.row.col.f32.bf16.bf16.f32 "
        "{%0,%1,%2,%3}, {%4,%5,%6,%7}, {%8,%9}, {%0,%1,%2,%3};"
        : "+f"(d[0]), "+f"(d[1]), "+f"(d[2]), "+f"(d[3])
        : "r"(a[0]), "r"(a[1]), "r"(a[2]), "r"(a[3]), "r"(b[0]), "r"(b[1]));
}

__device__ __forceinline__ float sigmoidf_(float v) {
    return 1.0f / (1.0f + __expf(-v));
}

// ---------------------------------------------------------------------------
// Combined conversion kernel:
//   blocks [0, 8192):      A = [x | h0]  -> gAhi/gAlo   (row-identity)
//   blocks [8192, 16384):  B = [wih|whh] -> gBhi/gBlo   (rows permuted j*4+g)
//   blocks [16384, 16400): permuted bias sum
// ---------------------------------------------------------------------------
__global__ __launch_bounds__(256)
void convert_all(const float* __restrict__ x,   const float* __restrict__ h0,
                 const float* __restrict__ wih, const float* __restrict__ whh,
                 const float* __restrict__ b_ih, const float* __restrict__ b_hh)
{
    const int bid = blockIdx.x;
    const int tid = threadIdx.x;

    if (bid >= 16384) {                       // bias
        const int np = (bid - 16384) * 256 + tid;        // 0..4095
        const int r = ((np & 3) << 10) | (np >> 2);      // orig row g*1024+j
        gBias[np] = b_ih[r] + b_hh[r];
        return;
    }

    const bool isA = (bid < 8192);
    const int idx = (isA ? bid : bid - 8192) * 256 + tid;  // 4-elem group id
    const int row = idx >> 9;                              // output row
    const int col = (idx & 511) << 2;                      // K column

    int srow = row;
    const float *s0, *s1;
    if (isA) { s0 = x; s1 = h0; }
    else     { s0 = wih; s1 = whh; srow = ((row & 3) << 10) | (row >> 2); }

    const float* src = (col < 1024) ? (s0 + (size_t)srow * 1024 + col)
                                    : (s1 + (size_t)srow * 1024 + (col - 1024));
    float4 v = *reinterpret_cast<const float4*>(src);
    float f[4] = {v.x, v.y, v.z, v.w};
    __nv_bfloat16 hb[4], lb[4];
    #pragma unroll
    for (int j = 0; j < 4; j++) {
        hb[j] = __float2bfloat16(f[j]);
        lb[j] = __float2bfloat16(f[j] - __bfloat162float(hb[j]));
    }
    __nv_bfloat16* hi = isA ? gAhi : gBhi;
    __nv_bfloat16* lo = isA ? gAlo : gBlo;
    const size_t o = (size_t)row * K_DIM + col;
    *reinterpret_cast<__nv_bfloat162*>(hi + o)     = __nv_bfloat162(hb[0], hb[1]);
    *reinterpret_cast<__nv_bfloat162*>(hi + o + 2) = __nv_bfloat162(hb[2], hb[3]);
    *reinterpret_cast<__nv_bfloat162*>(lo + o)     = __nv_bfloat162(lb[0], lb[1]);
    *reinterpret_cast<__nv_bfloat162*>(lo + o + 2) = __nv_bfloat162(lb[2], lb[3]);
}

// ---------------------------------------------------------------------------
// Fused GEMM + LSTM epilogue, 3 CTAs/SM (24 warps) to hide per-iter overhead.
//   gates = Ahi*Bhi^T + Ahi*Blo^T + Alo*Bhi^T  (gate-interleaved columns)
//   then per (b, j): c = sig(f)*c0 + sig(i)*tanh(g); h = sig(o)*tanh(c)
//
// SMEM tile layout: rows x 4 16B-chunks, chunk' = chunk ^ ((row>>1)&3).
// ---------------------------------------------------------------------------
__global__ __launch_bounds__(NTHREADS, 3)
void lstm_gemm_fused(const float* __restrict__ c0, float* __restrict__ out)
{
    extern __shared__ char smem[];
    const uint32_t sb = smem_u32(smem);
    const int tid  = threadIdx.x;
    const int wid  = tid >> 5;
    const int lane = tid & 31;
    const int warp_m = wid >> 1;    // 0..3
    const int warp_n = wid & 1;     // 0..1

    const int bm = blockIdx.y * BM;
    const int bn = blockIdx.x * BN;

    float acc[2][4][4];
    #pragma unroll
    for (int mt = 0; mt < 2; mt++)
        #pragma unroll
        for (int nt = 0; nt < 4; nt++)
            #pragma unroll
            for (int j = 0; j < 4; j++)
                acc[mt][nt][j] = 0.0f;

    // ---- ldmatrix addressing ----
    const int a_row = warp_m * 32 + (lane & 15);
    const int s_a   = (a_row >> 1) & 3;
    const int a_c0  = lane >> 4;                              // 0/1
    const int b_row = warp_n * 32 + ((lane >> 4) << 3) + (lane & 7);
    const int s_b   = (b_row >> 1) & 3;
    const int b_c0  = (lane >> 3) & 1;

    // ---- cp.async addressing ----
    const int r0 = tid >> 2;                 // 0..63
    const int cc = tid & 3;                  // 16B chunk
    const uint32_t dstoff = (uint32_t)(r0 * 64 + ((cc ^ ((r0 >> 1) & 3)) << 4));
    const __nv_bfloat16* pAhi = gAhi + (size_t)(bm + r0) * K_DIM + cc * 8;
    const __nv_bfloat16* pAlo = gAlo + (size_t)(bm + r0) * K_DIM + cc * 8;
    const __nv_bfloat16* pBhi = gBhi + (size_t)(bn + r0) * K_DIM + cc * 8;
    const __nv_bfloat16* pBlo = gBlo + (size_t)(bn + r0) * K_DIM + cc * 8;
    const size_t HSTEP = (size_t)64 * K_DIM;   // +64 rows (A tile second half)

    #define LOAD_STAGE(bufidx, k0) do {                                         \
        const uint32_t s_ = sb + (bufidx) * STAGE_BYTES + dstoff;               \
        CP_ASYNC16(s_,                      pAhi + (k0));                       \
        CP_ASYNC16(s_ + 4096,               pAhi + (k0) + HSTEP);               \
        CP_ASYNC16(s_ + OFF_ALO,            pAlo + (k0));                       \
        CP_ASYNC16(s_ + OFF_ALO + 4096,     pAlo + (k0) + HSTEP);               \
        CP_ASYNC16(s_ + OFF_BHI,            pBhi + (k0));                       \
        CP_ASYNC16(s_ + OFF_BLO,            pBlo + (k0));                       \
    } while (0)

    // prologue: stages 0,1
    LOAD_STAGE(0, 0);
    CP_COMMIT();
    LOAD_STAGE(1, BK);
    CP_COMMIT();

    int cbuf = 0, lbuf = 2;
    for (int t = 0; t < NT; t++) {
        CP_WAIT(1);
        __syncthreads();
        if (t + 2 < NT)
            LOAD_STAGE(lbuf, (t + 2) * BK);
        CP_COMMIT();

        const uint32_t stage = sb + cbuf * STAGE_BYTES;
        #pragma unroll
        for (int ks = 0; ks < 2; ks++) {
            uint32_t a_hi[2][4], a_lo[2][4];
            const int ca = ((ks * 2 + a_c0) ^ s_a) << 4;
            #pragma unroll
            for (int mt = 0; mt < 2; mt++) {
                const uint32_t aa = stage + (a_row + mt * 16) * 64 + ca;
                LDSM_X4(a_hi[mt], aa);
                LDSM_X4(a_lo[mt], aa + OFF_ALO);
            }
            const int cb = ((ks * 2 + b_c0) ^ s_b) << 4;
            #pragma unroll
            for (int g = 0; g < 2; g++) {
                uint32_t b_hi[4], b_lo[4];
                const uint32_t ba = stage + OFF_BHI + (b_row + g * 16) * 64 + cb;
                LDSM_X4(b_hi, ba);
                LDSM_X4(b_lo, ba + B_TILE_BYTES);
                // Pass-major: accumulator reuse distance = 4 MMAs
                #pragma unroll
                for (int mt = 0; mt < 2; mt++)
                    #pragma unroll
                    for (int h = 0; h < 2; h++)
                        mma_bf16(acc[mt][g * 2 + h], a_hi[mt], &b_hi[h * 2]);
                #pragma unroll
                for (int mt = 0; mt < 2; mt++)
                    #pragma unroll
                    for (int h = 0; h < 2; h++)
                        mma_bf16(acc[mt][g * 2 + h], a_hi[mt], &b_lo[h * 2]);
                #pragma unroll
                for (int mt = 0; mt < 2; mt++)
                    #pragma unroll
                    for (int h = 0; h < 2; h++)
                        mma_bf16(acc[mt][g * 2 + h], a_lo[mt], &b_hi[h * 2]);
            }
        }
        if (++cbuf == STAGES) cbuf = 0;
        if (++lbuf == STAGES) lbuf = 0;
    }

    // ---- fused LSTM epilogue ----
    const int q = lane & 3;
    const bool is_if = ((q & 1) == 0);

    float bsum[4][2];
    #pragma unroll
    for (int nt = 0; nt < 4; nt++) {
        const int c = bn + warp_n * 32 + nt * 8 + q * 2;
        bsum[nt][0] = gBias[c];
        bsum[nt][1] = gBias[c + 1];
    }

    #pragma unroll
    for (int mt = 0; mt < 2; mt++) {
        const int r = bm + warp_m * 32 + mt * 16 + (lane >> 2);
        #pragma unroll
        for (int nt = 0; nt < 4; nt++) {
            float v0 = acc[mt][nt][0] + bsum[nt][0];
            float v1 = acc[mt][nt][1] + bsum[nt][1];
            float v2 = acc[mt][nt][2] + bsum[nt][0];
            float v3 = acc[mt][nt][3] + bsum[nt][1];
            const float o0 = __shfl_xor_sync(0xffffffffu, v0, 1);
            const float o1 = __shfl_xor_sync(0xffffffffu, v1, 1);
            const float o2 = __shfl_xor_sync(0xffffffffu, v2, 1);
            const float o3 = __shfl_xor_sync(0xffffffffu, v3, 1);

            const float gi0 = is_if ? v0 : o0;
            const float gf0 = is_if ? v1 : o1;
            const float gg0 = is_if ? o0 : v0;
            const float go0 = is_if ? o1 : v1;
            const float gi1 = is_if ? v2 : o2;
            const float gf1 = is_if ? v3 : o3;
            const float gg1 = is_if ? o2 : v2;
            const float go1 = is_if ? o3 : v3;

            const int j = (bn >> 2) + warp_n * 8 + nt * 2 + (q >> 1);
            const float c0v0 = c0[(size_t)r * H_DIM + j];
            const float c0v1 = c0[(size_t)(r + 8) * H_DIM + j];

            const float cn0 = sigmoidf_(gf0) * c0v0 + sigmoidf_(gi0) * tanhf(gg0);
            const float cn1 = sigmoidf_(gf1) * c0v1 + sigmoidf_(gi1) * tanhf(gg1);
            const float hn0 = sigmoidf_(go0) * tanhf(cn0);
            const float hn1 = sigmoidf_(go1) * tanhf(cn1);

            if (is_if) {
                out[(size_t)r * H_DIM + j]       = hn0;
                out[(size_t)(r + 8) * H_DIM + j] = hn1;
            } else {
                out[(size_t)B_DIM * H_DIM + (size_t)r * H_DIM + j]       = cn0;
                out[(size_t)B_DIM * H_DIM + (size_t)(r + 8) * H_DIM + j] = cn1;
            }
        }
    }
    #undef LOAD_STAGE
}

// ---------------------------------------------------------------------------
// Launch
// ---------------------------------------------------------------------------
extern "C" void kernel_launch(void* const* d_in, const int* in_sizes, int n_in,
                              void* d_out, int out_size)
{
    const float* x    = (const float*)d_in[0];
    const float* h0   = (const float*)d_in[1];
    const float* c0   = (const float*)d_in[2];
    const float* wih  = (const float*)d_in[3];
    const float* whh  = (const float*)d_in[4];
    const float* b_ih = (const float*)d_in[5];
    const float* b_hh = (const float*)d_in[6];
    float* out = (float*)d_out;

    cudaFuncSetAttribute(lstm_gemm_fused,
                         cudaFuncAttributeMaxDynamicSharedMemorySize, SMEM_TOTAL);

    convert_all<<<16400, 256>>>(x, h0, wih, whh, b_ih, b_hh);

    dim3 grid(N_GATES / BN, B_DIM / BM);                 // (64, 32) = 2048 CTAs
    lstm_gemm_fused<<<grid, NTHREADS, SMEM_TOTAL>>>(c0, out);
}